// round 12
// baseline (speedup 1.0000x reference)
#include <cuda_runtime.h>
#include <cuda_fp16.h>
#include <cstdint>

#define N_NODES 50000
#define N_EDGES 1600000
#define FDIM    128
#define CAP     128          // per-node edge bucket capacity (max degree ~58)

#define GEMM_BLOCKS ((N_NODES + 127) / 128)          // 391
#define SCAT_BLOCKS ((N_EDGES / 4 + 255) / 256)      // 1563
#define WROW        36       // uint2 per column-row of packed W (pad: 36 % 16 == 4)

// Scratch (static __device__ arrays: allocation-free per harness rules)
static __device__ __half2 g_hh[(size_t)N_NODES * (FDIM / 2)];   // 12.8 MB
static __device__ float g_sd[N_NODES];
static __device__ float g_ss[N_NODES];
static __device__ int   g_cnt[N_NODES];
static __device__ int2  g_csr[(size_t)N_NODES * CAP];           // (src, score-bits)

#define FMA_F32X2(d, a, b, c) \
    asm("fma.rn.f32x2 %0, %1, %2, %3;" : "=l"(d) : "l"(a), "l"(b), "l"(c))

__device__ __forceinline__ unsigned long long pack_f2(float2 v) {
    return *reinterpret_cast<unsigned long long*>(&v);
}
__device__ __forceinline__ uint32_t f2_to_h2(float2 v) {
    __half2 h = __floats2half2_rn(v.x, v.y);
    return *reinterpret_cast<uint32_t*>(&h);
}

// ---------------------------------------------------------------------------
// GEMM + scores via HMMA (mma.sync m16n8k16 f16->f32), B-frags PRE-PAIRED:
// wp2[n*36 + kc*4 + t] = { h2(W[k0][n],W[k0+1][n]), h2(W[k0+8][n],W[k0+9][n]) }
// with k0 = kc*16 + 2t  ->  ONE LDS.64 per MMA instead of two LDS.32.
// Row stride 36 uint2 => each 16-lane phase hits distinct banks (36 mod 16 = 4).
// ---------------------------------------------------------------------------
__global__ __launch_bounds__(256) void gemm_score_mma(
    const float* __restrict__ X, const float* __restrict__ W,
    const float* __restrict__ attn)
{
    // fold counter zeroing into this kernel (scatter runs in a later launch)
    int zi = blockIdx.x * 128 + threadIdx.x;
    if (threadIdx.x < 128 && zi < N_NODES) g_cnt[zi] = 0;

    __shared__ __align__(16) uint2 wp2[FDIM * WROW];   // 36 KB

    for (int idx = threadIdx.x; idx < FDIM * 32; idx += 256) {
        int n  = idx >> 5;          // output column 0..127
        int j  = idx & 31;          // kc*4 + t
        int kc = j >> 2, t = j & 3;
        int k0 = kc * 16 + 2 * t;
        uint2 v;
        v.x = f2_to_h2(make_float2(W[(k0    ) * FDIM + n], W[(k0 + 1) * FDIM + n]));
        v.y = f2_to_h2(make_float2(W[(k0 + 8) * FDIM + n], W[(k0 + 9) * FDIM + n]));
        wp2[n * WROW + j] = v;
    }
    __syncthreads();

    const int warp = threadIdx.x >> 5;
    const int lane = threadIdx.x & 31;
    const int g = lane >> 2;       // group id (0..7)
    const int t = lane & 3;        // thread-in-group

    const int m0   = blockIdx.x * 128 + warp * 16;
    const int row0 = m0 + g;
    const int row1 = m0 + g + 8;
    const int lr0  = min(row0, N_NODES - 1);
    const int lr1  = min(row1, N_NODES - 1);

    const float* x0 = X + (size_t)lr0 * FDIM;
    const float* x1 = X + (size_t)lr1 * FDIM;

    float acc[16][4];
    #pragma unroll
    for (int nt = 0; nt < 16; nt++)
        acc[nt][0] = acc[nt][1] = acc[nt][2] = acc[nt][3] = 0.f;

    #pragma unroll
    for (int kc = 0; kc < 8; kc++) {
        int k0 = kc * 16 + 2 * t;
        uint32_t a0 = f2_to_h2(*reinterpret_cast<const float2*>(x0 + k0));
        uint32_t a1 = f2_to_h2(*reinterpret_cast<const float2*>(x1 + k0));
        uint32_t a2 = f2_to_h2(*reinterpret_cast<const float2*>(x0 + k0 + 8));
        uint32_t a3 = f2_to_h2(*reinterpret_cast<const float2*>(x1 + k0 + 8));
        #pragma unroll
        for (int nt = 0; nt < 16; nt++) {
            uint2 b = wp2[(nt * 8 + g) * WROW + kc * 4 + t];   // one LDS.64
            asm volatile(
                "mma.sync.aligned.m16n8k16.row.col.f32.f16.f16.f32 "
                "{%0,%1,%2,%3}, {%4,%5,%6,%7}, {%8,%9}, {%0,%1,%2,%3};"
                : "+f"(acc[nt][0]), "+f"(acc[nt][1]),
                  "+f"(acc[nt][2]), "+f"(acc[nt][3])
                : "r"(a0), "r"(a1), "r"(a2), "r"(a3), "r"(b.x), "r"(b.y));
        }
    }

    // Epilogue: h fp16 store + score partial dots
    float pd0 = 0.f, ps0 = 0.f, pd1 = 0.f, ps1 = 0.f;
    #pragma unroll
    for (int nt = 0; nt < 16; nt++) {
        int c0 = nt * 8 + 2 * t;                 // even -> 8B-aligned float2
        float2 ad = *reinterpret_cast<const float2*>(attn + c0);
        float2 as = *reinterpret_cast<const float2*>(attn + FDIM + c0);
        pd0 += acc[nt][0] * ad.x + acc[nt][1] * ad.y;
        ps0 += acc[nt][0] * as.x + acc[nt][1] * as.y;
        pd1 += acc[nt][2] * ad.x + acc[nt][3] * ad.y;
        ps1 += acc[nt][2] * as.x + acc[nt][3] * as.y;
        if (row0 < N_NODES)
            g_hh[(unsigned int)row0 * 64u + nt * 4 + t] =
                __floats2half2_rn(acc[nt][0], acc[nt][1]);
        if (row1 < N_NODES)
            g_hh[(unsigned int)row1 * 64u + nt * 4 + t] =
                __floats2half2_rn(acc[nt][2], acc[nt][3]);
    }
    // reduce across the 4 lanes of each group (t dimension)
    #pragma unroll
    for (int off = 1; off < 4; off <<= 1) {
        pd0 += __shfl_xor_sync(0xffffffffu, pd0, off);
        ps0 += __shfl_xor_sync(0xffffffffu, ps0, off);
        pd1 += __shfl_xor_sync(0xffffffffu, pd1, off);
        ps1 += __shfl_xor_sync(0xffffffffu, ps1, off);
    }
    if (t == 0) {
        if (row0 < N_NODES) { g_sd[row0] = pd0; g_ss[row0] = ps0; }
        if (row1 < N_NODES) { g_sd[row1] = pd1; g_ss[row1] = ps1; }
    }
}

// ---------------------------------------------------------------------------
// Scatter (measured-good form): 4 edges/thread, direct buckets.
// ---------------------------------------------------------------------------
__global__ __launch_bounds__(256) void scatter_kernel(const int4* __restrict__ E4) {
    int i = blockIdx.x * 256 + threadIdx.x;     // pair-of-pairs id
    if (i >= N_EDGES / 4) return;
    int4 ea = E4[i * 2];          // (dst0, src0, dst1, src1)
    int4 eb = E4[i * 2 + 1];      // (dst2, src2, dst3, src3)

    #define SCORE(D, S, OUTV) { \
        float sc = g_sd[D] + g_ss[S]; \
        sc = sc > 0.f ? sc : 0.2f * sc; \
        sc = fminf(2.f, fmaxf(-2.f, sc)); \
        OUTV = __expf(sc); }

    float s0, s1, s2, s3;
    SCORE(ea.x, ea.y, s0)
    SCORE(ea.z, ea.w, s1)
    SCORE(eb.x, eb.y, s2)
    SCORE(eb.z, eb.w, s3)
    #undef SCORE

    int p0 = atomicAdd(&g_cnt[ea.x], 1);
    int p1 = atomicAdd(&g_cnt[ea.z], 1);
    int p2 = atomicAdd(&g_cnt[eb.x], 1);
    int p3 = atomicAdd(&g_cnt[eb.z], 1);
    g_csr[(unsigned int)ea.x * CAP + p0] = make_int2(ea.y, __float_as_int(s0));
    g_csr[(unsigned int)ea.z * CAP + p1] = make_int2(ea.w, __float_as_int(s1));
    g_csr[(unsigned int)eb.x * CAP + p2] = make_int2(eb.y, __float_as_int(s2));
    g_csr[(unsigned int)eb.z * CAP + p3] = make_int2(eb.w, __float_as_int(s3));
}

// ---------------------------------------------------------------------------
// Agg (measured-good form): warp/node, 4 edges/iter, FFMA2 accum, 32-bit idx.
// ---------------------------------------------------------------------------
__global__ __launch_bounds__(256) void agg_kernel(float* __restrict__ out) {
    int w    = (blockIdx.x * blockDim.x + threadIdx.x) >> 5;
    int lane = threadIdx.x & 31;
    if (w >= N_NODES) return;

    int cnt = g_cnt[w];
    const int2* row = g_csr + (unsigned int)w * CAP;
    const uint2* hh = reinterpret_cast<const uint2*>(g_hh);

    unsigned long long accA = 0ull, accB = 0ull;   // packed (c0,c1), (c2,c3)
    float ssum = 0.f;

    #define ACCUM(V, WT) { \
        float2 f0 = __half22float2(*reinterpret_cast<__half2*>(&(V).x)); \
        float2 f1 = __half22float2(*reinterpret_cast<__half2*>(&(V).y)); \
        unsigned long long ww = pack_f2(make_float2((WT), (WT))); \
        FMA_F32X2(accA, ww, pack_f2(f0), accA); \
        FMA_F32X2(accB, ww, pack_f2(f1), accB); }

    int e = 0;
    for (; e + 4 <= cnt; e += 4) {
        int4 m01 = *reinterpret_cast<const int4*>(row + e);
        int4 m23 = *reinterpret_cast<const int4*>(row + e + 2);
        float w0 = __int_as_float(m01.y), w1 = __int_as_float(m01.w);
        float w2 = __int_as_float(m23.y), w3 = __int_as_float(m23.w);
        uint2 v0 = hh[(unsigned int)m01.x * 32u + lane];
        uint2 v1 = hh[(unsigned int)m01.z * 32u + lane];
        uint2 v2 = hh[(unsigned int)m23.x * 32u + lane];
        uint2 v3 = hh[(unsigned int)m23.z * 32u + lane];
        ACCUM(v0, w0) ACCUM(v1, w1) ACCUM(v2, w2) ACCUM(v3, w3)
        ssum += (w0 + w1) + (w2 + w3);
    }
    for (; e < cnt; e++) {
        int2 ee = row[e];
        float w0 = __int_as_float(ee.y);
        uint2 v0 = hh[(unsigned int)ee.x * 32u + lane];
        ACCUM(v0, w0)
        ssum += w0;
    }
    #undef ACCUM

    float2 rA = *reinterpret_cast<float2*>(&accA);
    float2 rB = *reinterpret_cast<float2*>(&accB);
    float inv = (ssum > 0.f) ? (1.f / ssum) : 0.f;
    reinterpret_cast<float4*>(out)[(unsigned int)w * 32u + lane] =
        make_float4(rA.x * inv, rA.y * inv, rB.x * inv, rB.y * inv);
}

// ---------------------------------------------------------------------------
extern "C" void kernel_launch(void* const* d_in, const int* in_sizes, int n_in,
                              void* d_out, int out_size)
{
    const float* X    = (const float*)d_in[0];   // node_states (50000,128)
    const int4*  E4   = (const int4*) d_in[1];   // edges as 2-edge packs
    const float* W    = (const float*)d_in[2];   // kernel (128,128)
    const float* attn = (const float*)d_in[3];   // kernel_attention (256,1)
    float* out = (float*)d_out;

    gemm_score_mma<<<GEMM_BLOCKS, 256>>>(X, W, attn);
    scatter_kernel<<<SCAT_BLOCKS, 256>>>(E4);
    agg_kernel<<<(N_NODES * 32 + 255) / 256, 256>>>(out);
}

// round 13
// speedup vs baseline: 1.1767x; 1.1767x over previous
#include <cuda_runtime.h>
#include <cuda_fp16.h>
#include <cstdint>

#define N_NODES 50000
#define N_EDGES 1600000
#define FDIM    128
#define CAP     128          // per-node edge bucket capacity (max degree ~58)

#define GEMM_BLOCKS ((N_NODES + 127) / 128)          // 391
#define SCAT_BLOCKS ((N_EDGES / 4 + 255) / 256)      // 1563
#define WPAD        136      // Wt row pad (halfs) -> conflict-free scalar LDS

// Scratch (static __device__ arrays: allocation-free per harness rules)
static __device__ __half2 g_hh[(size_t)N_NODES * (FDIM / 2)];   // 12.8 MB
static __device__ float g_sd[N_NODES];
static __device__ float g_ss[N_NODES];
static __device__ int   g_cnt[N_NODES];
static __device__ int2  g_csr[(size_t)N_NODES * CAP];           // (src, score-bits)

#define FMA_F32X2(d, a, b, c) \
    asm("fma.rn.f32x2 %0, %1, %2, %3;" : "=l"(d) : "l"(a), "l"(b), "l"(c))

__device__ __forceinline__ unsigned long long pack_f2(float2 v) {
    return *reinterpret_cast<unsigned long long*>(&v);
}
__device__ __forceinline__ uint32_t f2_to_h2(float2 v) {
    __half2 h = __floats2half2_rn(v.x, v.y);
    return *reinterpret_cast<uint32_t*>(&h);
}

// ---------------------------------------------------------------------------
// GEMM + scores via HMMA — EXACT round-11 measured-good form (25 us):
// Wt[n][k] fp16 smem, pad 136 halfs; two scalar LDS.32 per MMA (conflict-free:
// word addr 4g+t distinct across the warp). occ-limited but fastest measured.
// ---------------------------------------------------------------------------
__global__ __launch_bounds__(256) void gemm_score_mma(
    const float* __restrict__ X, const float* __restrict__ W,
    const float* __restrict__ attn)
{
    int zi = blockIdx.x * 128 + threadIdx.x;
    if (threadIdx.x < 128 && zi < N_NODES) g_cnt[zi] = 0;

    __shared__ __align__(16) __half wt[FDIM * WPAD];   // 34.8 KB

    for (int idx = threadIdx.x; idx < FDIM * FDIM; idx += 256) {
        int k = idx >> 7, n = idx & 127;
        wt[n * WPAD + k] = __float2half_rn(W[idx]);    // W[k][n] -> Wt[n][k]
    }
    __syncthreads();

    const int warp = threadIdx.x >> 5;
    const int lane = threadIdx.x & 31;
    const int g = lane >> 2;
    const int t = lane & 3;

    const int m0   = blockIdx.x * 128 + warp * 16;
    const int row0 = m0 + g;
    const int row1 = m0 + g + 8;
    const int lr0  = min(row0, N_NODES - 1);
    const int lr1  = min(row1, N_NODES - 1);

    const float* x0 = X + (size_t)lr0 * FDIM;
    const float* x1 = X + (size_t)lr1 * FDIM;
    const uint32_t* wtw = reinterpret_cast<const uint32_t*>(wt);   // 68 words/row

    float acc[16][4];
    #pragma unroll
    for (int nt = 0; nt < 16; nt++)
        acc[nt][0] = acc[nt][1] = acc[nt][2] = acc[nt][3] = 0.f;

    #pragma unroll
    for (int kc = 0; kc < 8; kc++) {
        int k0 = kc * 16 + 2 * t;
        uint32_t a0 = f2_to_h2(*reinterpret_cast<const float2*>(x0 + k0));
        uint32_t a1 = f2_to_h2(*reinterpret_cast<const float2*>(x1 + k0));
        uint32_t a2 = f2_to_h2(*reinterpret_cast<const float2*>(x0 + k0 + 8));
        uint32_t a3 = f2_to_h2(*reinterpret_cast<const float2*>(x1 + k0 + 8));
        #pragma unroll
        for (int nt = 0; nt < 16; nt++) {
            int bw = (nt * 8 + g) * (WPAD / 2) + kc * 8 + t;
            uint32_t b0 = wtw[bw];
            uint32_t b1 = wtw[bw + 4];
            asm volatile(
                "mma.sync.aligned.m16n8k16.row.col.f32.f16.f16.f32 "
                "{%0,%1,%2,%3}, {%4,%5,%6,%7}, {%8,%9}, {%0,%1,%2,%3};"
                : "+f"(acc[nt][0]), "+f"(acc[nt][1]),
                  "+f"(acc[nt][2]), "+f"(acc[nt][3])
                : "r"(a0), "r"(a1), "r"(a2), "r"(a3), "r"(b0), "r"(b1));
        }
    }

    float pd0 = 0.f, ps0 = 0.f, pd1 = 0.f, ps1 = 0.f;
    #pragma unroll
    for (int nt = 0; nt < 16; nt++) {
        int c0 = nt * 8 + 2 * t;
        float2 ad = *reinterpret_cast<const float2*>(attn + c0);
        float2 as = *reinterpret_cast<const float2*>(attn + FDIM + c0);
        pd0 += acc[nt][0] * ad.x + acc[nt][1] * ad.y;
        ps0 += acc[nt][0] * as.x + acc[nt][1] * as.y;
        pd1 += acc[nt][2] * ad.x + acc[nt][3] * ad.y;
        ps1 += acc[nt][2] * as.x + acc[nt][3] * as.y;
        if (row0 < N_NODES)
            g_hh[(unsigned int)row0 * 64u + nt * 4 + t] =
                __floats2half2_rn(acc[nt][0], acc[nt][1]);
        if (row1 < N_NODES)
            g_hh[(unsigned int)row1 * 64u + nt * 4 + t] =
                __floats2half2_rn(acc[nt][2], acc[nt][3]);
    }
    #pragma unroll
    for (int off = 1; off < 4; off <<= 1) {
        pd0 += __shfl_xor_sync(0xffffffffu, pd0, off);
        ps0 += __shfl_xor_sync(0xffffffffu, ps0, off);
        pd1 += __shfl_xor_sync(0xffffffffu, pd1, off);
        ps1 += __shfl_xor_sync(0xffffffffu, ps1, off);
    }
    if (t == 0) {
        if (row0 < N_NODES) { g_sd[row0] = pd0; g_ss[row0] = ps0; }
        if (row1 < N_NODES) { g_sd[row1] = pd1; g_ss[row1] = ps1; }
    }
}

// ---------------------------------------------------------------------------
// Scatter (measured-good form): 4 edges/thread, direct buckets.
// ---------------------------------------------------------------------------
__global__ __launch_bounds__(256) void scatter_kernel(const int4* __restrict__ E4) {
    int i = blockIdx.x * 256 + threadIdx.x;
    if (i >= N_EDGES / 4) return;
    int4 ea = E4[i * 2];
    int4 eb = E4[i * 2 + 1];

    #define SCORE(D, S, OUTV) { \
        float sc = g_sd[D] + g_ss[S]; \
        sc = sc > 0.f ? sc : 0.2f * sc; \
        sc = fminf(2.f, fmaxf(-2.f, sc)); \
        OUTV = __expf(sc); }

    float s0, s1, s2, s3;
    SCORE(ea.x, ea.y, s0)
    SCORE(ea.z, ea.w, s1)
    SCORE(eb.x, eb.y, s2)
    SCORE(eb.z, eb.w, s3)
    #undef SCORE

    int p0 = atomicAdd(&g_cnt[ea.x], 1);
    int p1 = atomicAdd(&g_cnt[ea.z], 1);
    int p2 = atomicAdd(&g_cnt[eb.x], 1);
    int p3 = atomicAdd(&g_cnt[eb.z], 1);
    g_csr[(unsigned int)ea.x * CAP + p0] = make_int2(ea.y, __float_as_int(s0));
    g_csr[(unsigned int)ea.z * CAP + p1] = make_int2(ea.w, __float_as_int(s1));
    g_csr[(unsigned int)eb.x * CAP + p2] = make_int2(eb.y, __float_as_int(s2));
    g_csr[(unsigned int)eb.z * CAP + p3] = make_int2(eb.w, __float_as_int(s3));
}

// ---------------------------------------------------------------------------
// Agg: one warp per node, EDGES PAIRED ACROSS HALF-WARPS (uniform control
// flow). Lane loads uint4 (8 fp16 cols) of its half's edge -> gather LDG
// count per edge halves vs round-10. Odd tail = zero-weight phantom edge.
// shfl_xor(16) combine once per node.
// ---------------------------------------------------------------------------
__global__ __launch_bounds__(256) void agg_kernel(float* __restrict__ out) {
    int w    = (blockIdx.x * blockDim.x + threadIdx.x) >> 5;
    int lane = threadIdx.x & 31;
    if (w >= N_NODES) return;

    const int half = lane >> 4;      // 0: even edges, 1: odd edges
    const int hl   = lane & 15;      // column-chunk id (8 cols each)
    int cnt = g_cnt[w];
    const int2* row = g_csr + (unsigned int)w * CAP;
    const uint4* hh4 = reinterpret_cast<const uint4*>(g_hh);   // 16 uint4 / node

    unsigned long long a01 = 0ull, a23 = 0ull, a45 = 0ull, a67 = 0ull;
    float ssum = 0.f;

    #define ACCUM4(V, WT) { \
        unsigned long long ww = pack_f2(make_float2((WT), (WT))); \
        float2 f0 = __half22float2(*reinterpret_cast<__half2*>(&(V).x)); \
        float2 f1 = __half22float2(*reinterpret_cast<__half2*>(&(V).y)); \
        float2 f2 = __half22float2(*reinterpret_cast<__half2*>(&(V).z)); \
        float2 f3 = __half22float2(*reinterpret_cast<__half2*>(&(V).w)); \
        FMA_F32X2(a01, ww, pack_f2(f0), a01); \
        FMA_F32X2(a23, ww, pack_f2(f1), a23); \
        FMA_F32X2(a45, ww, pack_f2(f2), a45); \
        FMA_F32X2(a67, ww, pack_f2(f3), a67); }

    int e = 0;
    for (; e + 4 <= cnt; e += 4) {
        int4 m01 = *reinterpret_cast<const int4*>(row + e);       // edges e, e+1
        int4 m23 = *reinterpret_cast<const int4*>(row + e + 2);   // edges e+2, e+3
        int   s0 = half ? m01.z : m01.x;
        float w0 = __int_as_float(half ? m01.w : m01.y);
        int   s1 = half ? m23.z : m23.x;
        float w1 = __int_as_float(half ? m23.w : m23.y);
        uint4 v0 = hh4[(unsigned int)s0 * 16u + hl];
        uint4 v1 = hh4[(unsigned int)s1 * 16u + hl];
        ACCUM4(v0, w0) ACCUM4(v1, w1)
        ssum += w0 + w1;
    }
    for (; e + 2 <= cnt; e += 2) {
        int4 m01 = *reinterpret_cast<const int4*>(row + e);
        int   s0 = half ? m01.z : m01.x;
        float w0 = __int_as_float(half ? m01.w : m01.y);
        uint4 v0 = hh4[(unsigned int)s0 * 16u + hl];
        ACCUM4(v0, w0)
        ssum += w0;
    }
    if (e < cnt) {                    // odd tail: half 1 runs a phantom edge
        int2 ee = row[e];
        int   s0 = half ? 0 : ee.x;
        float w0 = half ? 0.f : __int_as_float(ee.y);
        uint4 v0 = hh4[(unsigned int)s0 * 16u + hl];
        ACCUM4(v0, w0)
        ssum += w0;
    }
    #undef ACCUM4

    // combine the two half-warps (lane i <-> i^16 hold the same 8 columns)
    float2 c0 = *reinterpret_cast<float2*>(&a01);
    float2 c1 = *reinterpret_cast<float2*>(&a23);
    float2 c2 = *reinterpret_cast<float2*>(&a45);
    float2 c3 = *reinterpret_cast<float2*>(&a67);
    c0.x += __shfl_xor_sync(0xffffffffu, c0.x, 16);
    c0.y += __shfl_xor_sync(0xffffffffu, c0.y, 16);
    c1.x += __shfl_xor_sync(0xffffffffu, c1.x, 16);
    c1.y += __shfl_xor_sync(0xffffffffu, c1.y, 16);
    c2.x += __shfl_xor_sync(0xffffffffu, c2.x, 16);
    c2.y += __shfl_xor_sync(0xffffffffu, c2.y, 16);
    c3.x += __shfl_xor_sync(0xffffffffu, c3.x, 16);
    c3.y += __shfl_xor_sync(0xffffffffu, c3.y, 16);
    ssum += __shfl_xor_sync(0xffffffffu, ssum, 16);

    float inv = (ssum > 0.f) ? (1.f / ssum) : 0.f;
    // lane's 8 columns = [hl*8, hl*8+8); half 0 stores first 4, half 1 last 4
    float4 r = half ? make_float4(c2.x * inv, c2.y * inv, c3.x * inv, c3.y * inv)
                    : make_float4(c0.x * inv, c0.y * inv, c1.x * inv, c1.y * inv);
    reinterpret_cast<float4*>(out)[(unsigned int)w * 32u + hl * 2 + half] = r;
}

// ---------------------------------------------------------------------------
extern "C" void kernel_launch(void* const* d_in, const int* in_sizes, int n_in,
                              void* d_out, int out_size)
{
    const float* X    = (const float*)d_in[0];   // node_states (50000,128)
    const int4*  E4   = (const int4*) d_in[1];   // edges as 2-edge packs
    const float* W    = (const float*)d_in[2];   // kernel (128,128)
    const float* attn = (const float*)d_in[3];   // kernel_attention (256,1)
    float* out = (float*)d_out;

    gemm_score_mma<<<GEMM_BLOCKS, 256>>>(X, W, attn);
    scatter_kernel<<<SCAT_BLOCKS, 256>>>(E4);
    agg_kernel<<<(N_NODES * 32 + 255) / 256, 256>>>(out);
}

// round 14
// speedup vs baseline: 1.2281x; 1.0437x over previous
#include <cuda_runtime.h>
#include <cuda_fp16.h>
#include <cstdint>

#define N_NODES 50000
#define N_EDGES 1600000
#define FDIM    128
#define CAP     128          // per-node edge bucket capacity (max degree ~58)

#define GEMM_BLOCKS ((N_NODES + 63) / 64)            // 782 (64 rows per block)
#define SCAT_BLOCKS ((N_EDGES / 4 + 255) / 256)      // 1563
#define PREP_BLOCKS 196
#define WPAD        136      // Wt row pad (halfs) -> conflict-free scalar LDS
#define WT_U4       ((FDIM * WPAD) / 8)              // 2176 uint4

// Scratch (static __device__ arrays: allocation-free per harness rules)
static __device__ __half2 g_hh[(size_t)N_NODES * (FDIM / 2)];   // 12.8 MB
static __device__ float g_sd[N_NODES];
static __device__ float g_ss[N_NODES];
static __device__ uint4 g_wt4[WT_U4];                            // packed fp16 Wt
static __device__ int   g_cnt[N_NODES];
static __device__ int2  g_csr[(size_t)N_NODES * CAP];           // (src, score-bits)

#define FMA_F32X2(d, a, b, c) \
    asm("fma.rn.f32x2 %0, %1, %2, %3;" : "=l"(d) : "l"(a), "l"(b), "l"(c))

__device__ __forceinline__ unsigned long long pack_f2(float2 v) {
    return *reinterpret_cast<unsigned long long*>(&v);
}
__device__ __forceinline__ uint32_t f2_to_h2(float2 v) {
    __half2 h = __floats2half2_rn(v.x, v.y);
    return *reinterpret_cast<uint32_t*>(&h);
}

// ---------------------------------------------------------------------------
// Prep: pack W -> fp16 Wt[n][k] (WPAD layout) in global; zero bucket counters.
// ---------------------------------------------------------------------------
__global__ __launch_bounds__(256) void prep_kernel(const float* __restrict__ W) {
    int i = blockIdx.x * 256 + threadIdx.x;
    if (i < FDIM * FDIM) {
        int k = i >> 7, n = i & 127;
        reinterpret_cast<__half*>(g_wt4)[n * WPAD + k] = __float2half_rn(W[i]);
    }
    if (i < N_NODES) g_cnt[i] = 0;
}

// ---------------------------------------------------------------------------
// GEMM + scores via HMMA, N-SPLIT ACROSS WARP PAIRS:
// warp = 16 rows x 64 cols (nt = sub*8 + 0..7), acc regs halved vs round-11
// -> 4 CTAs/SM. Block covers 64 rows. Score dots: per-warp partials combined
// via smem across the warp pair.
// ---------------------------------------------------------------------------
__global__ __launch_bounds__(256, 4) void gemm_score_mma(
    const float* __restrict__ X, const float* __restrict__ attn)
{
    __shared__ __align__(16) __half wt[FDIM * WPAD];   // 34.8 KB
    __shared__ float sred[8][16][2];                   // [warp][row][pd,ps]

    {   // fast fill: copy pre-packed Wt as uint4
        const uint4* s = g_wt4;
        uint4* d = reinterpret_cast<uint4*>(wt);
        #pragma unroll
        for (int r = 0; r < 9; r++) {
            int i = r * 256 + threadIdx.x;
            if (i < WT_U4) d[i] = s[i];
        }
    }
    __syncthreads();

    const int warp = threadIdx.x >> 5;
    const int lane = threadIdx.x & 31;
    const int pair = warp >> 1;        // 0..3 (16 rows each)
    const int sub  = warp & 1;         // 0: cols 0-63, 1: cols 64-127
    const int g = lane >> 2;
    const int t = lane & 3;

    const int m0   = blockIdx.x * 64 + pair * 16;
    const int row0 = m0 + g;
    const int row1 = m0 + g + 8;
    const int lr0  = min(row0, N_NODES - 1);
    const int lr1  = min(row1, N_NODES - 1);

    const float* x0 = X + (size_t)lr0 * FDIM;
    const float* x1 = X + (size_t)lr1 * FDIM;
    const uint32_t* wtw = reinterpret_cast<const uint32_t*>(wt);   // 68 words/row

    float acc[8][4];
    #pragma unroll
    for (int n = 0; n < 8; n++)
        acc[n][0] = acc[n][1] = acc[n][2] = acc[n][3] = 0.f;

    #pragma unroll
    for (int kc = 0; kc < 8; kc++) {
        int k0 = kc * 16 + 2 * t;
        uint32_t a0 = f2_to_h2(*reinterpret_cast<const float2*>(x0 + k0));
        uint32_t a1 = f2_to_h2(*reinterpret_cast<const float2*>(x1 + k0));
        uint32_t a2 = f2_to_h2(*reinterpret_cast<const float2*>(x0 + k0 + 8));
        uint32_t a3 = f2_to_h2(*reinterpret_cast<const float2*>(x1 + k0 + 8));
        #pragma unroll
        for (int ntl = 0; ntl < 8; ntl++) {
            int nt = sub * 8 + ntl;
            int bw = (nt * 8 + g) * (WPAD / 2) + kc * 8 + t;   // 4g+t: conflict-free
            uint32_t b0 = wtw[bw];
            uint32_t b1 = wtw[bw + 4];
            asm volatile(
                "mma.sync.aligned.m16n8k16.row.col.f32.f16.f16.f32 "
                "{%0,%1,%2,%3}, {%4,%5,%6,%7}, {%8,%9}, {%0,%1,%2,%3};"
                : "+f"(acc[ntl][0]), "+f"(acc[ntl][1]),
                  "+f"(acc[ntl][2]), "+f"(acc[ntl][3])
                : "r"(a0), "r"(a1), "r"(a2), "r"(a3), "r"(b0), "r"(b1));
        }
    }

    // Epilogue: h fp16 store + partial score dots over this warp's 64 cols
    float pd0 = 0.f, ps0 = 0.f, pd1 = 0.f, ps1 = 0.f;
    #pragma unroll
    for (int ntl = 0; ntl < 8; ntl++) {
        int nt = sub * 8 + ntl;
        int c0 = nt * 8 + 2 * t;
        float2 ad = *reinterpret_cast<const float2*>(attn + c0);
        float2 as = *reinterpret_cast<const float2*>(attn + FDIM + c0);
        pd0 += acc[ntl][0] * ad.x + acc[ntl][1] * ad.y;
        ps0 += acc[ntl][0] * as.x + acc[ntl][1] * as.y;
        pd1 += acc[ntl][2] * ad.x + acc[ntl][3] * ad.y;
        ps1 += acc[ntl][2] * as.x + acc[ntl][3] * as.y;
        if (row0 < N_NODES)
            g_hh[(unsigned int)row0 * 64u + nt * 4 + t] =
                __floats2half2_rn(acc[ntl][0], acc[ntl][1]);
        if (row1 < N_NODES)
            g_hh[(unsigned int)row1 * 64u + nt * 4 + t] =
                __floats2half2_rn(acc[ntl][2], acc[ntl][3]);
    }
    #pragma unroll
    for (int off = 1; off < 4; off <<= 1) {
        pd0 += __shfl_xor_sync(0xffffffffu, pd0, off);
        ps0 += __shfl_xor_sync(0xffffffffu, ps0, off);
        pd1 += __shfl_xor_sync(0xffffffffu, pd1, off);
        ps1 += __shfl_xor_sync(0xffffffffu, ps1, off);
    }
    if (t == 0) {
        sred[warp][g][0]     = pd0;  sred[warp][g][1]     = ps0;
        sred[warp][g + 8][0] = pd1;  sred[warp][g + 8][1] = ps1;
    }
    __syncthreads();

    // combine warp pairs and store scores: 4 pairs x 16 rows x 2 comps = 128
    if (threadIdx.x < 128) {
        int p    = threadIdx.x >> 5;
        int r    = (threadIdx.x >> 1) & 15;
        int comp = threadIdx.x & 1;
        int grow = blockIdx.x * 64 + p * 16 + r;
        if (grow < N_NODES) {
            float v = sred[2 * p][r][comp] + sred[2 * p + 1][r][comp];
            if (comp == 0) g_sd[grow] = v; else g_ss[grow] = v;
        }
    }
}

// ---------------------------------------------------------------------------
// Scatter (measured-good form): 4 edges/thread, direct buckets.
// ---------------------------------------------------------------------------
__global__ __launch_bounds__(256) void scatter_kernel(const int4* __restrict__ E4) {
    int i = blockIdx.x * 256 + threadIdx.x;
    if (i >= N_EDGES / 4) return;
    int4 ea = E4[i * 2];
    int4 eb = E4[i * 2 + 1];

    #define SCORE(D, S, OUTV) { \
        float sc = g_sd[D] + g_ss[S]; \
        sc = sc > 0.f ? sc : 0.2f * sc; \
        sc = fminf(2.f, fmaxf(-2.f, sc)); \
        OUTV = __expf(sc); }

    float s0, s1, s2, s3;
    SCORE(ea.x, ea.y, s0)
    SCORE(ea.z, ea.w, s1)
    SCORE(eb.x, eb.y, s2)
    SCORE(eb.z, eb.w, s3)
    #undef SCORE

    int p0 = atomicAdd(&g_cnt[ea.x], 1);
    int p1 = atomicAdd(&g_cnt[ea.z], 1);
    int p2 = atomicAdd(&g_cnt[eb.x], 1);
    int p3 = atomicAdd(&g_cnt[eb.z], 1);
    g_csr[(unsigned int)ea.x * CAP + p0] = make_int2(ea.y, __float_as_int(s0));
    g_csr[(unsigned int)ea.z * CAP + p1] = make_int2(ea.w, __float_as_int(s1));
    g_csr[(unsigned int)eb.x * CAP + p2] = make_int2(eb.y, __float_as_int(s2));
    g_csr[(unsigned int)eb.z * CAP + p3] = make_int2(eb.w, __float_as_int(s3));
}

// ---------------------------------------------------------------------------
// Agg (round-10 measured-good form — FINAL): warp/node, 4 edges/iter,
// FFMA2 accum, 32-bit indexing.
// ---------------------------------------------------------------------------
__global__ __launch_bounds__(256) void agg_kernel(float* __restrict__ out) {
    int w    = (blockIdx.x * blockDim.x + threadIdx.x) >> 5;
    int lane = threadIdx.x & 31;
    if (w >= N_NODES) return;

    int cnt = g_cnt[w];
    const int2* row = g_csr + (unsigned int)w * CAP;
    const uint2* hh = reinterpret_cast<const uint2*>(g_hh);

    unsigned long long accA = 0ull, accB = 0ull;
    float ssum = 0.f;

    #define ACCUM(V, WT) { \
        float2 f0 = __half22float2(*reinterpret_cast<__half2*>(&(V).x)); \
        float2 f1 = __half22float2(*reinterpret_cast<__half2*>(&(V).y)); \
        unsigned long long ww = pack_f2(make_float2((WT), (WT))); \
        FMA_F32X2(accA, ww, pack_f2(f0), accA); \
        FMA_F32X2(accB, ww, pack_f2(f1), accB); }

    int e = 0;
    for (; e + 4 <= cnt; e += 4) {
        int4 m01 = *reinterpret_cast<const int4*>(row + e);
        int4 m23 = *reinterpret_cast<const int4*>(row + e + 2);
        float w0 = __int_as_float(m01.y), w1 = __int_as_float(m01.w);
        float w2 = __int_as_float(m23.y), w3 = __int_as_float(m23.w);
        uint2 v0 = hh[(unsigned int)m01.x * 32u + lane];
        uint2 v1 = hh[(unsigned int)m01.z * 32u + lane];
        uint2 v2 = hh[(unsigned int)m23.x * 32u + lane];
        uint2 v3 = hh[(unsigned int)m23.z * 32u + lane];
        ACCUM(v0, w0) ACCUM(v1, w1) ACCUM(v2, w2) ACCUM(v3, w3)
        ssum += (w0 + w1) + (w2 + w3);
    }
    for (; e < cnt; e++) {
        int2 ee = row[e];
        float w0 = __int_as_float(ee.y);
        uint2 v0 = hh[(unsigned int)ee.x * 32u + lane];
        ACCUM(v0, w0)
        ssum += w0;
    }
    #undef ACCUM

    float2 rA = *reinterpret_cast<float2*>(&accA);
    float2 rB = *reinterpret_cast<float2*>(&accB);
    float inv = (ssum > 0.f) ? (1.f / ssum) : 0.f;
    reinterpret_cast<float4*>(out)[(unsigned int)w * 32u + lane] =
        make_float4(rA.x * inv, rA.y * inv, rB.x * inv, rB.y * inv);
}

// ---------------------------------------------------------------------------
extern "C" void kernel_launch(void* const* d_in, const int* in_sizes, int n_in,
                              void* d_out, int out_size)
{
    const float* X    = (const float*)d_in[0];   // node_states (50000,128)
    const int4*  E4   = (const int4*) d_in[1];   // edges as 2-edge packs
    const float* W    = (const float*)d_in[2];   // kernel (128,128)
    const float* attn = (const float*)d_in[3];   // kernel_attention (256,1)
    float* out = (float*)d_out;

    prep_kernel<<<PREP_BLOCKS, 256>>>(W);
    gemm_score_mma<<<GEMM_BLOCKS, 256>>>(X, attn);
    scatter_kernel<<<SCAT_BLOCKS, 256>>>(E4);
    agg_kernel<<<(N_NODES * 32 + 255) / 256, 256>>>(out);
}